// round 2
// baseline (speedup 1.0000x reference)
#include <cuda_runtime.h>
#include <math.h>

// Problem constants (fixed shapes)
#define NROWS 8192
#define DDIM  128
#define BM    64
#define BN    128
#define PAD   132          // row pitch in floats (8B/16B aligned, bank-friendly)
#define NTHREADS 256
#define ALPHA 2.0f

__device__ double g_supcon;
__device__ double g_pt;

__global__ void esup_zero_kernel() {
    g_supcon = 0.0;
    g_pt = 0.0;
}

// Packed fp32x2 FMA (Blackwell FFMA2): d = a*b + c elementwise on 2 floats.
#define FMA_F32X2(d, a, b, c) \
    asm("fma.rn.f32x2 %0, %1, %2, %3;" : "=l"(d) : "l"(a), "l"(b), "l"(c))

static __device__ __forceinline__ float fold2(unsigned long long v) {
    float lo, hi;
    asm("mov.b64 {%0, %1}, %2;" : "=f"(lo), "=f"(hi) : "l"(v));
    return lo + hi;
}

__global__ __launch_bounds__(NTHREADS, 1)
void esup_main_kernel(const float* __restrict__ z_au,
                      const float* __restrict__ z_tp,
                      const float* __restrict__ fc) {
    extern __shared__ float smem[];
    float* sAau = smem;                    // [BM][PAD]
    float* sAtp = sAau + BM * PAD;         // [BM][PAD]
    float* sBau = sAtp + BM * PAD;         // [BN][PAD]
    float* sBtp = sBau + BN * PAD;         // [BN][PAD]

    const int tid = threadIdx.x;
    const int tx = tid & 15;               // 0..15  -> column group
    const int ty = tid >> 4;               // 0..15  -> row group
    const int i0 = blockIdx.x * BM;

    // ---- Load A tiles (this CTA's 64 rows of z_au / z_tp), once ----
    {
        const int colq = tid & 31;         // float4 index along D
        const int row0 = tid >> 5;         // 0..7
        #pragma unroll
        for (int it = 0; it < BM / 8; ++it) {
            int row = row0 + it * 8;
            const float4 va = *(const float4*)(z_au + (size_t)(i0 + row) * DDIM + colq * 4);
            const float4 vt = *(const float4*)(z_tp + (size_t)(i0 + row) * DDIM + colq * 4);
            *(float4*)(sAau + row * PAD + colq * 4) = va;
            *(float4*)(sAtp + row * PAD + colq * 4) = vt;
        }
    }

    // Per-thread online logsumexp state for its 4 rows (row = ty + 16*r)
    float mpos[4], lpos[4], mneg[4], lneg[4];
    #pragma unroll
    for (int r = 0; r < 4; ++r) {
        mpos[r] = -1e30f; lpos[r] = 0.0f;
        mneg[r] = -1e30f; lneg[r] = 0.0f;
    }

    // ---- Stream over column tiles ----
    for (int jt = 0; jt < NROWS / BN; ++jt) {
        const int j0 = jt * BN;
        __syncthreads();   // previous tile's compute done before overwriting B
        {
            const int colq = tid & 31;
            const int row0 = tid >> 5;
            #pragma unroll
            for (int it = 0; it < BN / 8; ++it) {
                int row = row0 + it * 8;
                const float4 va = *(const float4*)(z_au + (size_t)(j0 + row) * DDIM + colq * 4);
                const float4 vt = *(const float4*)(z_tp + (size_t)(j0 + row) * DDIM + colq * 4);
                *(float4*)(sBau + row * PAD + colq * 4) = va;
                *(float4*)(sBtp + row * PAD + colq * 4) = vt;
            }
        }
        __syncthreads();

        // ---- 4x8 micro-tile, 3 similarity matrices, packed f32x2 along k ----
        // Each accumulator holds {sum over even k-slots, sum over odd k-slots}.
        unsigned long long aa[4][8], tt[4][8], at[4][8];
        #pragma unroll
        for (int r = 0; r < 4; ++r)
            #pragma unroll
            for (int c = 0; c < 8; ++c) { aa[r][c] = 0ull; tt[r][c] = 0ull; at[r][c] = 0ull; }

        const float* pAau = sAau + ty * PAD;
        const float* pAtp = sAtp + ty * PAD;
        const float* pBau = sBau + tx * PAD;
        const float* pBtp = sBtp + tx * PAD;

        #pragma unroll 2
        for (int k = 0; k < DDIM; k += 2) {
            unsigned long long a_au[4], a_tp[4];
            #pragma unroll
            for (int r = 0; r < 4; ++r) {
                a_au[r] = *(const unsigned long long*)(pAau + (16 * r) * PAD + k);
                a_tp[r] = *(const unsigned long long*)(pAtp + (16 * r) * PAD + k);
            }
            #pragma unroll
            for (int c = 0; c < 8; ++c) {
                const unsigned long long b_au = *(const unsigned long long*)(pBau + (16 * c) * PAD + k);
                const unsigned long long b_tp = *(const unsigned long long*)(pBtp + (16 * c) * PAD + k);
                #pragma unroll
                for (int r = 0; r < 4; ++r) {
                    FMA_F32X2(aa[r][c], a_au[r], b_au, aa[r][c]);
                    FMA_F32X2(tt[r][c], a_tp[r], b_tp, tt[r][c]);
                    FMA_F32X2(at[r][c], a_au[r], b_tp, at[r][c]);
                }
            }
        }

        // ---- Online logsumexp update with diagonal masking ----
        #pragma unroll
        for (int r = 0; r < 4; ++r) {
            const int gi = i0 + ty + 16 * r;
            float va[8], vt[8], vn[8];
            float vmaxp = -1e30f, vmaxn = -1e30f;
            #pragma unroll
            for (int c = 0; c < 8; ++c) {
                const int gj = j0 + tx + 16 * c;
                const bool dm = (gj == gi);
                va[c] = dm ? -1e30f : fold2(aa[r][c]);
                vt[c] = dm ? -1e30f : fold2(tt[r][c]);
                vn[c] = dm ? -1e30f : fold2(at[r][c]);
                vmaxp = fmaxf(vmaxp, fmaxf(va[c], vt[c]));
                vmaxn = fmaxf(vmaxn, vn[c]);
            }
            // pos stream (aa + tt combined)
            float nm = fmaxf(mpos[r], vmaxp);
            float s = lpos[r] * __expf(mpos[r] - nm);
            #pragma unroll
            for (int c = 0; c < 8; ++c) s += __expf(va[c] - nm) + __expf(vt[c] - nm);
            lpos[r] = s; mpos[r] = nm;
            // neg stream (at)
            nm = fmaxf(mneg[r], vmaxn);
            s = lneg[r] * __expf(mneg[r] - nm);
            #pragma unroll
            for (int c = 0; c < 8; ++c) s += __expf(vn[c] - nm);
            lneg[r] = s; mneg[r] = nm;
        }
    }

    __syncthreads();

    // ---- Stash per-thread stats into SMEM (reuse B region) ----
    float* sStat = sBau;                   // [64][16][4] = 4096 floats
    #pragma unroll
    for (int r = 0; r < 4; ++r) {
        const int row = ty + 16 * r;
        float* p = sStat + (row * 16 + tx) * 4;
        p[0] = mpos[r]; p[1] = lpos[r]; p[2] = mneg[r]; p[3] = lneg[r];
    }

    // ---- Diagonal (au_i . tp_i) and prototype partials (reuse sBtp) ----
    float* sDiag = sBtp;                   // [64][4]
    float* sPt   = sBtp + 256;             // [64][4]
    {
        const int row = tid & 63;
        const int part = tid >> 6;         // 0..3
        const int kb = part * 32;
        float dsum = 0.f, psum = 0.f;
        #pragma unroll 8
        for (int kk = 0; kk < 32; ++kk) {
            const int k = kb + kk;
            const float a = sAau[row * PAD + k];
            const float b = sAtp[row * PAD + k];
            const float w = fc[DDIM + k] - fc[k];   // pt1 - pt0
            dsum += a * b;
            psum += (a - b) * w;
        }
        sDiag[row * 4 + part] = dsum;
        sPt[row * 4 + part]   = psum;
    }
    __syncthreads();

    float* sRow = sBtp + 512;              // [64]
    float* sPtr = sBtp + 576;              // [64]
    if (tid < 64) {
        const int row = tid;
        float M = -1e30f, L = 0.f, Mn = -1e30f, Ln = 0.f;
        for (int t = 0; t < 16; ++t) {
            const float* p = sStat + (row * 16 + t) * 4;
            float m = p[0], l = p[1];
            if (m > M) { L = L * __expf(M - m) + l; M = m; }
            else       { L += l * __expf(m - M); }
            m = p[2]; l = p[3];
            if (m > Mn) { Ln = Ln * __expf(Mn - m) + l; Mn = m; }
            else        { Ln += l * __expf(m - Mn); }
        }
        const float pos = M + logf(L);
        const float neg = Mn + logf(Ln);
        const float diag = sDiag[row * 4 + 0] + sDiag[row * 4 + 1] +
                           sDiag[row * 4 + 2] + sDiag[row * 4 + 3];
        const float pt   = sPt[row * 4 + 0] + sPt[row * 4 + 1] +
                           sPt[row * 4 + 2] + sPt[row * 4 + 3];
        sRow[row] = -pos + neg + ALPHA * diag;
        sPtr[row] = pt;
    }
    __syncthreads();

    if (tid == 0) {
        double s = 0.0, p = 0.0;
        for (int i = 0; i < 64; ++i) { s += (double)sRow[i]; p += (double)sPtr[i]; }
        atomicAdd(&g_supcon, s);
        atomicAdd(&g_pt, p);
    }
}

__global__ void esup_finalize_kernel(float* out) {
    out[0] = (float)((g_pt / (double)NROWS + g_supcon) / (double)(NROWS + 2));
}

extern "C" void kernel_launch(void* const* d_in, const int* in_sizes, int n_in,
                              void* d_out, int out_size) {
    const float* z_au = (const float*)d_in[0];
    const float* z_tp = (const float*)d_in[1];
    const float* fc   = (const float*)d_in[2];
    // d_in[3] = labels (int64) — unused by the math.
    float* out = (float*)d_out;

    const size_t smembytes = (size_t)(2 * BM * PAD + 2 * BN * PAD) * sizeof(float); // 202752
    cudaFuncSetAttribute(esup_main_kernel,
                         cudaFuncAttributeMaxDynamicSharedMemorySize, (int)smembytes);

    esup_zero_kernel<<<1, 1>>>();
    esup_main_kernel<<<NROWS / BM, NTHREADS, smembytes>>>(z_au, z_tp, fc);
    esup_finalize_kernel<<<1, 1>>>(out);
}

// round 4
// speedup vs baseline: 15.1621x; 15.1621x over previous
#include <cuda_runtime.h>
#include <cuda_fp16.h>
#include <math.h>
#include <stdint.h>

#define NR 8192
#define DD 128
#define ALPHA 2.0f
#define EXPBIAS 96.0f

// ---------------- device globals ----------------
__device__ __align__(128) __half g_au_hi[NR * DD];
__device__ __align__(128) __half g_au_lo[NR * DD];
__device__ __align__(128) __half g_tp_hi[NR * DD];
__device__ __align__(128) __half g_tp_lo[NR * DD];
__device__ float g_pos[NR];    // sum_j exp(s_aa - B) + exp(s_tt - B), j != i
__device__ float g_neg[NR];    // sum_j exp(s_at - B), j != i
__device__ double g_supcon;
__device__ double g_pt;

// ---------------- small kernels ----------------
__global__ void esup_zero_kernel() {
    const int i = blockIdx.x * blockDim.x + threadIdx.x;
    if (i < NR) { g_pos[i] = 0.0f; g_neg[i] = 0.0f; }
    if (i == 0) { g_supcon = 0.0; g_pt = 0.0; }
}

__global__ void esup_split_kernel(const float* __restrict__ z_au,
                                  const float* __restrict__ z_tp) {
    const int i = blockIdx.x * blockDim.x + threadIdx.x;
    if (i < NR * DD) {
        const float a = z_au[i];
        const __half h = __float2half_rn(a);
        g_au_hi[i] = h;
        g_au_lo[i] = __float2half_rn(a - __half2float(h));
        const float b = z_tp[i];
        const __half g = __float2half_rn(b);
        g_tp_hi[i] = g;
        g_tp_lo[i] = __float2half_rn(b - __half2float(g));
    }
}

// ---------------- PTX helpers (baseline ISA only: sm_80-era) ----------------
__device__ __forceinline__ uint32_t smem_u32(const void* p) {
    uint32_t a;
    asm("{ .reg .u64 t; cvta.to.shared.u64 t, %1; cvt.u32.u64 %0, t; }" : "=r"(a) : "l"(p));
    return a;
}

#define CP_ASYNC16(dst_u32, src_ptr) \
    asm volatile("cp.async.cg.shared.global [%0], [%1], 16;" \
        :: "r"(dst_u32), "l"(src_ptr) : "memory")
#define CP_COMMIT() asm volatile("cp.async.commit_group;" ::: "memory")
#define CP_WAIT1()  asm volatile("cp.async.wait_group 1;" ::: "memory")
#define CP_WAIT0()  asm volatile("cp.async.wait_group 0;" ::: "memory")

__device__ __forceinline__ void ldsm_x4(uint32_t* r, uint32_t addr) {
    asm volatile("ldmatrix.sync.aligned.m8n8.x4.shared.b16 {%0,%1,%2,%3}, [%4];"
        : "=r"(r[0]), "=r"(r[1]), "=r"(r[2]), "=r"(r[3]) : "r"(addr));
}

__device__ __forceinline__ void mma16816(float* c, const uint32_t* a,
                                         uint32_t b0, uint32_t b1) {
    asm volatile("mma.sync.aligned.m16n8k16.row.col.f32.f16.f16.f32 "
        "{%0,%1,%2,%3}, {%4,%5,%6,%7}, {%8,%9}, {%0,%1,%2,%3};"
        : "+f"(c[0]), "+f"(c[1]), "+f"(c[2]), "+f"(c[3])
        : "r"(a[0]), "r"(a[1]), "r"(a[2]), "r"(a[3]), "r"(b0), "r"(b1));
}

// smem tile: [128 rows][16 chunks of 16B], chunk xor-swizzled by (row & 7)
__device__ __forceinline__ uint32_t tile_off(int row, int c) {
    return (uint32_t)(row * 256 + ((c ^ (row & 7)) << 4));
}

// ---------------- main fused GEMM + exp-sum kernel ----------------
// smem: A hi [0,32K), A lo [32K,64K), B stage s: 64K + s*64K (hi/lo same split)
#define SM_A 0u
#define SM_B 65536u
#define SMEM_BYTES 196608

__global__ __launch_bounds__(256, 1) void esup_mma_kernel() {
    extern __shared__ char smem[];
    const uint32_t sb = smem_u32(smem);
    const int tid = threadIdx.x;
    const int lane = tid & 31;
    const int wid = tid >> 5;
    const int wrow = wid & 3;        // 4 warp-rows of 32
    const int wcol = wid >> 2;       // 2 warp-cols of 64

    // bid -> (job, row tile, j-chunk of 4 tiles)
    const int bid = blockIdx.x;
    const int job = bid >> 10;               // 0:aa 1:tt 2:at
    const int rem = bid & 1023;
    const int i0 = (rem >> 4) * 128;
    const int j0base = (rem & 15) * 512;

    const __half *Ahi_g, *Alo_g, *Bhi_g, *Blo_g;
    if (job == 0)      { Ahi_g = g_au_hi; Alo_g = g_au_lo; Bhi_g = g_au_hi; Blo_g = g_au_lo; }
    else if (job == 1) { Ahi_g = g_tp_hi; Alo_g = g_tp_lo; Bhi_g = g_tp_hi; Blo_g = g_tp_lo; }
    else               { Ahi_g = g_au_hi; Alo_g = g_au_lo; Bhi_g = g_tp_hi; Blo_g = g_tp_lo; }

    // ---- group 0: A tile (hi+lo) + B tile 0 ----
    #pragma unroll
    for (int it = 0; it < 16; ++it) {
        const int idx = tid + it * 256;              // 0..4095
        const int mat = idx >> 11;                   // 0=hi 1=lo
        const int r2 = idx & 2047;
        const int row = r2 >> 4, c = r2 & 15;
        const __half* s = (mat ? Alo_g : Ahi_g) + (size_t)(i0 + row) * DD + c * 8;
        CP_ASYNC16(sb + SM_A + mat * 32768u + tile_off(row, c), s);
    }
    #pragma unroll
    for (int it = 0; it < 16; ++it) {
        const int idx = tid + it * 256;
        const int mat = idx >> 11;
        const int r2 = idx & 2047;
        const int row = r2 >> 4, c = r2 & 15;
        const __half* s = (mat ? Blo_g : Bhi_g) + (size_t)(j0base + row) * DD + c * 8;
        CP_ASYNC16(sb + SM_B + mat * 32768u + tile_off(row, c), s);
    }
    CP_COMMIT();

    // persistent per-thread row exp-sums: [mt][rh]
    float rs[2][2] = {{0.f, 0.f}, {0.f, 0.f}};

    for (int t = 0; t < 4; ++t) {
        // prefetch next B tile into other stage
        if (t < 3) {
            const uint32_t stg = sb + SM_B + ((t + 1) & 1) * 65536u;
            const int j0n = j0base + (t + 1) * 128;
            #pragma unroll
            for (int it = 0; it < 16; ++it) {
                const int idx = tid + it * 256;
                const int mat = idx >> 11;
                const int r2 = idx & 2047;
                const int row = r2 >> 4, c = r2 & 15;
                const __half* s = (mat ? Blo_g : Bhi_g) + (size_t)(j0n + row) * DD + c * 8;
                CP_ASYNC16(stg + mat * 32768u + tile_off(row, c), s);
            }
            CP_COMMIT();
            CP_WAIT1();
        } else {
            CP_WAIT0();
        }
        __syncthreads();

        const uint32_t bsb = sb + SM_B + (t & 1) * 65536u;
        const int j0 = j0base + t * 128;

        float acc[2][8][4];
        #pragma unroll
        for (int mt = 0; mt < 2; ++mt)
            #pragma unroll
            for (int nt = 0; nt < 8; ++nt)
                #pragma unroll
                for (int q = 0; q < 4; ++q) acc[mt][nt][q] = 0.f;

        #pragma unroll
        for (int ks = 0; ks < 8; ++ks) {
            // A fragments (hi & lo): rows = wrow*32 + mt*16 + (lane&15), chunk = ks*2 + (lane>>4)
            uint32_t Ah[2][4], Al[2][4];
            const int arow = wrow * 32 + (lane & 15);
            const int ac = ks * 2 + (lane >> 4);
            #pragma unroll
            for (int mt = 0; mt < 2; ++mt) {
                const int r = arow + mt * 16;
                const uint32_t off = tile_off(r, ac);
                ldsm_x4(Ah[mt], sb + SM_A + off);
                ldsm_x4(Al[mt], sb + SM_A + 32768u + off);
            }
            // B fragments: n = wcol*64 + nt2*16 + ((lane>>4)<<3) + (lane&7), chunk = ks*2 + ((lane>>3)&1)
            uint32_t Bh[4][4], Bl[4][4];
            const int bn = wcol * 64 + ((lane >> 4) << 3) + (lane & 7);
            const int bc = ks * 2 + ((lane >> 3) & 1);
            #pragma unroll
            for (int nt2 = 0; nt2 < 4; ++nt2) {
                const int n = bn + nt2 * 16;
                const uint32_t off = tile_off(n, bc);
                ldsm_x4(Bh[nt2], bsb + off);
                ldsm_x4(Bl[nt2], bsb + 32768u + off);
            }
            #pragma unroll
            for (int mt = 0; mt < 2; ++mt) {
                #pragma unroll
                for (int nt = 0; nt < 8; ++nt) {
                    const uint32_t* bh = &Bh[nt >> 1][(nt & 1) * 2];
                    const uint32_t* bl = &Bl[nt >> 1][(nt & 1) * 2];
                    mma16816(acc[mt][nt], Ah[mt], bh[0], bh[1]);  // hi*hi
                    mma16816(acc[mt][nt], Ah[mt], bl[0], bl[1]);  // hi*lo
                    mma16816(acc[mt][nt], Al[mt], bh[0], bh[1]);  // lo*hi
                }
            }
        }
        __syncthreads();   // stage (t&1) consumed; safe to overwrite at t+1

        // ---- epilogue: exp(v - BIAS), diag mask, per-row sums ----
        const bool dt = (i0 == j0);
        #pragma unroll
        for (int mt = 0; mt < 2; ++mt) {
            #pragma unroll
            for (int rh = 0; rh < 2; ++rh) {
                float s = 0.f;
                const int gr = i0 + wrow * 32 + mt * 16 + rh * 8 + (lane >> 2);
                #pragma unroll
                for (int nt = 0; nt < 8; ++nt) {
                    #pragma unroll
                    for (int cc = 0; cc < 2; ++cc) {
                        float v = acc[mt][nt][rh * 2 + cc];
                        if (dt) {
                            const int gc = j0 + wcol * 64 + nt * 8 + (lane & 3) * 2 + cc;
                            if (gr == gc) v = -1e30f;
                        }
                        s += __expf(v - EXPBIAS);
                    }
                }
                rs[mt][rh] += s;
            }
        }
    }

    // ---- quad reduce + global atomics ----
    float* dst = (job == 2) ? g_neg : g_pos;
    #pragma unroll
    for (int mt = 0; mt < 2; ++mt) {
        #pragma unroll
        for (int rh = 0; rh < 2; ++rh) {
            float s = rs[mt][rh];
            s += __shfl_xor_sync(0xFFFFFFFF, s, 1);
            s += __shfl_xor_sync(0xFFFFFFFF, s, 2);
            if ((lane & 3) == 0) {
                const int gr = i0 + wrow * 32 + mt * 16 + rh * 8 + (lane >> 2);
                atomicAdd(dst + gr, s);
            }
        }
    }
}

// ---------------- per-row reduction (exact fp32 parts + lse assembly) ----------------
__global__ void esup_rowreduce_kernel(const float* __restrict__ z_au,
                                      const float* __restrict__ z_tp,
                                      const float* __restrict__ fc) {
    __shared__ float sv[128], sp[128];
    const int row = blockIdx.x * 128 + threadIdx.x;

    const float pos = EXPBIAS + logf(g_pos[row]);
    const float neg = EXPBIAS + logf(g_neg[row]);

    float diag = 0.f, pt = 0.f;
    const float4* pa = (const float4*)(z_au + (size_t)row * DD);
    const float4* pb = (const float4*)(z_tp + (size_t)row * DD);
    #pragma unroll
    for (int q = 0; q < 32; ++q) {
        const float4 a = pa[q], b = pb[q];
        const float4 w0 = *(const float4*)(fc + q * 4);
        const float4 w1 = *(const float4*)(fc + DD + q * 4);
        diag += a.x * b.x + a.y * b.y + a.z * b.z + a.w * b.w;
        pt += (a.x - b.x) * (w1.x - w0.x) + (a.y - b.y) * (w1.y - w0.y) +
              (a.z - b.z) * (w1.z - w0.z) + (a.w - b.w) * (w1.w - w0.w);
    }

    sv[threadIdx.x] = -pos + neg + ALPHA * diag;
    sp[threadIdx.x] = pt;
    __syncthreads();
    if (threadIdx.x == 0) {
        double s = 0.0, p = 0.0;
        for (int i = 0; i < 128; ++i) { s += (double)sv[i]; p += (double)sp[i]; }
        atomicAdd(&g_supcon, s);
        atomicAdd(&g_pt, p);
    }
}

__global__ void esup_finalize_kernel(float* out) {
    out[0] = (float)((g_pt / (double)NR + g_supcon) / (double)(NR + 2));
}

// ---------------- launch ----------------
extern "C" void kernel_launch(void* const* d_in, const int* in_sizes, int n_in,
                              void* d_out, int out_size) {
    const float* z_au = (const float*)d_in[0];
    const float* z_tp = (const float*)d_in[1];
    const float* fc   = (const float*)d_in[2];
    float* out = (float*)d_out;

    cudaFuncSetAttribute(esup_mma_kernel,
                         cudaFuncAttributeMaxDynamicSharedMemorySize, SMEM_BYTES);

    esup_zero_kernel<<<32, 256>>>();
    esup_split_kernel<<<(NR * DD + 255) / 256, 256>>>(z_au, z_tp);
    esup_mma_kernel<<<3072, 256, SMEM_BYTES>>>();
    esup_rowreduce_kernel<<<NR / 128, 128>>>(z_au, z_tp, fc);
    esup_finalize_kernel<<<1, 1>>>(out);
}

// round 5
// speedup vs baseline: 24.2781x; 1.6012x over previous
#include <cuda_runtime.h>
#include <cuda_fp16.h>
#include <math.h>
#include <stdint.h>

#define NR 8192
#define DD 128
#define ALPHA 2.0f
#define EXPBIAS 96.0f

// ---------------- device globals ----------------
__device__ __align__(128) __half g_au_hi[NR * DD];
__device__ __align__(128) __half g_au_lo[NR * DD];
__device__ __align__(128) __half g_tp_hi[NR * DD];
__device__ __align__(128) __half g_tp_lo[NR * DD];
__device__ float g_pos[NR];    // sum_{j!=i} exp(s_aa-B) + exp(s_tt-B)
__device__ float g_neg[NR];    // sum_{j!=i} exp(s_at-B)
__device__ double g_supcon;
__device__ double g_pt;

// ---------------- split (+zero) kernel: 4 elems/thread ----------------
__global__ void esup_split_kernel(const float* __restrict__ z_au,
                                  const float* __restrict__ z_tp) {
    const int t4 = blockIdx.x * blockDim.x + threadIdx.x;   // 0..262143
    const int base = t4 * 4;
    if (t4 < NR) { g_pos[t4] = 0.0f; g_neg[t4] = 0.0f; }
    if (t4 == 0) { g_supcon = 0.0; g_pt = 0.0; }

    const float4 a = *(const float4*)(z_au + base);
    const float4 b = *(const float4*)(z_tp + base);

    __half h[4], l[4];
    const float af[4] = {a.x, a.y, a.z, a.w};
    #pragma unroll
    for (int q = 0; q < 4; ++q) {
        h[q] = __float2half_rn(af[q]);
        l[q] = __float2half_rn(af[q] - __half2float(h[q]));
    }
    ((__half2*)(g_au_hi + base))[0] = __halves2half2(h[0], h[1]);
    ((__half2*)(g_au_hi + base))[1] = __halves2half2(h[2], h[3]);
    ((__half2*)(g_au_lo + base))[0] = __halves2half2(l[0], l[1]);
    ((__half2*)(g_au_lo + base))[1] = __halves2half2(l[2], l[3]);

    const float bf[4] = {b.x, b.y, b.z, b.w};
    #pragma unroll
    for (int q = 0; q < 4; ++q) {
        h[q] = __float2half_rn(bf[q]);
        l[q] = __float2half_rn(bf[q] - __half2float(h[q]));
    }
    ((__half2*)(g_tp_hi + base))[0] = __halves2half2(h[0], h[1]);
    ((__half2*)(g_tp_hi + base))[1] = __halves2half2(h[2], h[3]);
    ((__half2*)(g_tp_lo + base))[0] = __halves2half2(l[0], l[1]);
    ((__half2*)(g_tp_lo + base))[1] = __halves2half2(l[2], l[3]);
}

// ---------------- PTX helpers (baseline ISA, compiles at compute_103) ----------------
__device__ __forceinline__ uint32_t smem_u32(const void* p) {
    uint32_t a;
    asm("{ .reg .u64 t; cvta.to.shared.u64 t, %1; cvt.u32.u64 %0, t; }" : "=r"(a) : "l"(p));
    return a;
}

#define CP_ASYNC16(dst_u32, src_ptr) \
    asm volatile("cp.async.cg.shared.global [%0], [%1], 16;" \
        :: "r"(dst_u32), "l"(src_ptr) : "memory")
#define CP_COMMIT() asm volatile("cp.async.commit_group;" ::: "memory")
#define CP_WAIT1()  asm volatile("cp.async.wait_group 1;" ::: "memory")
#define CP_WAIT0()  asm volatile("cp.async.wait_group 0;" ::: "memory")

__device__ __forceinline__ void ldsm_x4(uint32_t* r, uint32_t addr) {
    asm volatile("ldmatrix.sync.aligned.m8n8.x4.shared.b16 {%0,%1,%2,%3}, [%4];"
        : "=r"(r[0]), "=r"(r[1]), "=r"(r[2]), "=r"(r[3]) : "r"(addr));
}

__device__ __forceinline__ void mma16816(float* c, const uint32_t* a,
                                         uint32_t b0, uint32_t b1) {
    asm volatile("mma.sync.aligned.m16n8k16.row.col.f32.f16.f16.f32 "
        "{%0,%1,%2,%3}, {%4,%5,%6,%7}, {%8,%9}, {%0,%1,%2,%3};"
        : "+f"(c[0]), "+f"(c[1]), "+f"(c[2]), "+f"(c[3])
        : "r"(a[0]), "r"(a[1]), "r"(a[2]), "r"(a[3]), "r"(b0), "r"(b1));
}

// smem tile: [128 rows][16 chunks of 16B], chunk xor-swizzled by (row & 7)
__device__ __forceinline__ uint32_t tile_off(int row, int c) {
    return (uint32_t)(row * 256 + ((c ^ (row & 7)) << 4));
}

// ---------------- main fused GEMM + exp-sum kernel ----------------
// smem: A_hi [0,32K); B stage s at 32K + s*64K (hi at +0, lo at +32K); scol at 160K.
#define SM_A   0u
#define SM_B   32768u
#define SM_COL 163840u
#define SMEM_BYTES 165888

// grid layout: [0,544) job aa triangular, [544,1088) job tt triangular,
// [1088,2112) job at rectangular (64 row tiles x 16 chunks of 4 col tiles)
__global__ __launch_bounds__(256, 1) void esup_mma_kernel() {
    extern __shared__ char smem[];
    const uint32_t sb = smem_u32(smem);
    float* scol = (float*)(smem + SM_COL);       // [512]
    const int tid = threadIdx.x;
    const int lane = tid & 31;
    const int wid = tid >> 5;
    const int wrow = wid & 3;        // 4 warp-rows of 32
    const int wcol = wid >> 2;       // 2 warp-cols of 64

    // ---- bid -> (job, row tile it, chunk) ----
    int job, it, chunk;
    {
        const int bid = blockIdx.x;
        if (bid < 1088) {
            job = (bid < 544) ? 0 : 1;
            int s = (bid < 544) ? bid : bid - 544;
            int itv = 0;
            while (true) {
                const int w = 16 - (itv >> 2);
                if (s < w) break;
                s -= w; ++itv;
            }
            it = itv;
            chunk = (it >> 2) + s;
        } else {
            job = 2;
            const int r = bid - 1088;
            it = r >> 4;
            chunk = r & 15;
        }
    }
    const int i0 = it * 128;
    const int j0base = chunk * 512;

    const __half *Ahi_g, *Bhi_g, *Blo_g;
    if (job == 0)      { Ahi_g = g_au_hi; Bhi_g = g_au_hi; Blo_g = g_au_lo; }
    else if (job == 1) { Ahi_g = g_tp_hi; Bhi_g = g_tp_hi; Blo_g = g_tp_lo; }
    else               { Ahi_g = g_au_hi; Bhi_g = g_tp_hi; Blo_g = g_tp_lo; }

    // zero column accumulator
    scol[tid] = 0.0f;
    scol[tid + 256] = 0.0f;

    // ---- group 0: A_hi tile + B tile 0 (hi+lo) ----
    #pragma unroll
    for (int itr = 0; itr < 8; ++itr) {
        const int idx = tid + itr * 256;             // 0..2047
        const int row = idx >> 4, c = idx & 15;
        const __half* s = Ahi_g + (size_t)(i0 + row) * DD + c * 8;
        CP_ASYNC16(sb + SM_A + tile_off(row, c), s);
    }
    #pragma unroll
    for (int itr = 0; itr < 16; ++itr) {
        const int idx = tid + itr * 256;             // 0..4095
        const int mat = idx >> 11;                   // 0=hi 1=lo
        const int r2 = idx & 2047;
        const int row = r2 >> 4, c = r2 & 15;
        const __half* s = (mat ? Blo_g : Bhi_g) + (size_t)(j0base + row) * DD + c * 8;
        CP_ASYNC16(sb + SM_B + mat * 32768u + tile_off(row, c), s);
    }
    CP_COMMIT();

    // persistent per-thread row exp-sums: [mt][rh]
    float rs[2][2] = {{0.f, 0.f}, {0.f, 0.f}};

    for (int t = 0; t < 4; ++t) {
        // prefetch next B tile into other stage
        if (t < 3) {
            const uint32_t stg = sb + SM_B + ((t + 1) & 1) * 65536u;
            const int j0n = j0base + (t + 1) * 128;
            #pragma unroll
            for (int itr = 0; itr < 16; ++itr) {
                const int idx = tid + itr * 256;
                const int mat = idx >> 11;
                const int r2 = idx & 2047;
                const int row = r2 >> 4, c = r2 & 15;
                const __half* s = (mat ? Blo_g : Bhi_g) + (size_t)(j0n + row) * DD + c * 8;
                CP_ASYNC16(stg + mat * 32768u + tile_off(row, c), s);
            }
            CP_COMMIT();
            CP_WAIT1();
        } else {
            CP_WAIT0();
        }
        __syncthreads();

        const uint32_t bsb = sb + SM_B + (t & 1) * 65536u;
        const int j0 = j0base + t * 128;
        const int jt = chunk * 4 + t;

        float acc[2][8][4];
        #pragma unroll
        for (int mt = 0; mt < 2; ++mt)
            #pragma unroll
            for (int nt = 0; nt < 8; ++nt)
                #pragma unroll
                for (int q = 0; q < 4; ++q) acc[mt][nt][q] = 0.f;

        #pragma unroll
        for (int ks = 0; ks < 8; ++ks) {
            uint32_t Ah[2][4];
            const int arow = wrow * 32 + (lane & 15);
            const int ac = ks * 2 + (lane >> 4);
            #pragma unroll
            for (int mt = 0; mt < 2; ++mt)
                ldsm_x4(Ah[mt], sb + SM_A + tile_off(arow + mt * 16, ac));

            uint32_t Bh[4][4], Bl[4][4];
            const int bn = wcol * 64 + ((lane >> 4) << 3) + (lane & 7);
            const int bc = ks * 2 + ((lane >> 3) & 1);
            #pragma unroll
            for (int nt2 = 0; nt2 < 4; ++nt2) {
                const uint32_t off = tile_off(bn + nt2 * 16, bc);
                ldsm_x4(Bh[nt2], bsb + off);
                ldsm_x4(Bl[nt2], bsb + 32768u + off);
            }
            #pragma unroll
            for (int mt = 0; mt < 2; ++mt) {
                #pragma unroll
                for (int nt = 0; nt < 8; ++nt) {
                    const uint32_t* bh = &Bh[nt >> 1][(nt & 1) * 2];
                    const uint32_t* bl = &Bl[nt >> 1][(nt & 1) * 2];
                    mma16816(acc[mt][nt], Ah[mt], bh[0], bh[1]);  // hi*hi
                    mma16816(acc[mt][nt], Ah[mt], bl[0], bl[1]);  // hi*lo
                }
            }
        }
        __syncthreads();   // stage (t&1) consumed

        // ---- epilogue ----
        const bool do_row = (job == 2) || (jt >= it);
        const bool do_col = (job != 2) && (jt > it);
        const bool dt = (jt == it);
        if (do_row) {
            #pragma unroll
            for (int nt = 0; nt < 8; ++nt) {
                float c0 = 0.f, c1 = 0.f;
                #pragma unroll
                for (int mt = 0; mt < 2; ++mt) {
                    #pragma unroll
                    for (int rh = 0; rh < 2; ++rh) {
                        float v0 = acc[mt][nt][rh * 2 + 0];
                        float v1 = acc[mt][nt][rh * 2 + 1];
                        if (dt) {
                            const int gr = i0 + wrow * 32 + mt * 16 + rh * 8 + (lane >> 2);
                            const int gc0 = j0 + wcol * 64 + nt * 8 + (lane & 3) * 2;
                            if (gr == gc0) v0 = -1e30f;
                            if (gr == gc0 + 1) v1 = -1e30f;
                        }
                        const float e0 = __expf(v0 - EXPBIAS);
                        const float e1 = __expf(v1 - EXPBIAS);
                        rs[mt][rh] += e0 + e1;
                        c0 += e0; c1 += e1;
                    }
                }
                if (do_col) {
                    // reduce over the 8 lanes sharing (lane & 3): bits 2..4
                    c0 += __shfl_xor_sync(0xFFFFFFFF, c0, 4);
                    c0 += __shfl_xor_sync(0xFFFFFFFF, c0, 8);
                    c0 += __shfl_xor_sync(0xFFFFFFFF, c0, 16);
                    c1 += __shfl_xor_sync(0xFFFFFFFF, c1, 4);
                    c1 += __shfl_xor_sync(0xFFFFFFFF, c1, 8);
                    c1 += __shfl_xor_sync(0xFFFFFFFF, c1, 16);
                    if (lane < 4) {
                        const int lc = t * 128 + wcol * 64 + nt * 8 + lane * 2;
                        atomicAdd(&scol[lc], c0);
                        atomicAdd(&scol[lc + 1], c1);
                    }
                }
            }
        }
    }

    // ---- row flush: quad reduce + global atomics ----
    float* dst = (job == 2) ? g_neg : g_pos;
    #pragma unroll
    for (int mt = 0; mt < 2; ++mt) {
        #pragma unroll
        for (int rh = 0; rh < 2; ++rh) {
            float s = rs[mt][rh];
            s += __shfl_xor_sync(0xFFFFFFFF, s, 1);
            s += __shfl_xor_sync(0xFFFFFFFF, s, 2);
            if ((lane & 3) == 0) {
                const int gr = i0 + wrow * 32 + mt * 16 + rh * 8 + (lane >> 2);
                atomicAdd(dst + gr, s);
            }
        }
    }

    // ---- column flush (symmetric jobs: transpose contribution) ----
    __syncthreads();
    if (job != 2) {
        #pragma unroll
        for (int q = 0; q < 2; ++q) {
            const int idx = tid + q * 256;
            const float v = scol[idx];
            if (v != 0.0f) atomicAdd(&g_pos[j0base + idx], v);
        }
    }
}

// ---------------- per-row reduction: warp per row ----------------
__global__ void esup_rowreduce_kernel(const float* __restrict__ z_au,
                                      const float* __restrict__ z_tp,
                                      const float* __restrict__ fc) {
    __shared__ float sv[8], sp[8];
    const int lane = threadIdx.x & 31;
    const int wid = threadIdx.x >> 5;
    const int row = blockIdx.x * 8 + wid;

    const float4 a = *(const float4*)(z_au + (size_t)row * DD + lane * 4);
    const float4 b = *(const float4*)(z_tp + (size_t)row * DD + lane * 4);
    const float4 w0 = *(const float4*)(fc + lane * 4);
    const float4 w1 = *(const float4*)(fc + DD + lane * 4);

    float diag = a.x * b.x + a.y * b.y + a.z * b.z + a.w * b.w;
    float pt = (a.x - b.x) * (w1.x - w0.x) + (a.y - b.y) * (w1.y - w0.y) +
               (a.z - b.z) * (w1.z - w0.z) + (a.w - b.w) * (w1.w - w0.w);
    #pragma unroll
    for (int s = 16; s > 0; s >>= 1) {
        diag += __shfl_xor_sync(0xFFFFFFFF, diag, s);
        pt   += __shfl_xor_sync(0xFFFFFFFF, pt, s);
    }
    if (lane == 0) {
        const float pos = EXPBIAS + logf(g_pos[row]);
        const float neg = EXPBIAS + logf(g_neg[row]);
        sv[wid] = -pos + neg + ALPHA * diag;
        sp[wid] = pt;
    }
    __syncthreads();
    if (threadIdx.x == 0) {
        double s = 0.0, p = 0.0;
        #pragma unroll
        for (int i = 0; i < 8; ++i) { s += (double)sv[i]; p += (double)sp[i]; }
        atomicAdd(&g_supcon, s);
        atomicAdd(&g_pt, p);
    }
}

__global__ void esup_finalize_kernel(float* out) {
    out[0] = (float)((g_pt / (double)NR + g_supcon) / (double)(NR + 2));
}

// ---------------- launch ----------------
extern "C" void kernel_launch(void* const* d_in, const int* in_sizes, int n_in,
                              void* d_out, int out_size) {
    const float* z_au = (const float*)d_in[0];
    const float* z_tp = (const float*)d_in[1];
    const float* fc   = (const float*)d_in[2];
    float* out = (float*)d_out;

    cudaFuncSetAttribute(esup_mma_kernel,
                         cudaFuncAttributeMaxDynamicSharedMemorySize, SMEM_BYTES);

    esup_split_kernel<<<(NR * DD / 4) / 256, 256>>>(z_au, z_tp);
    esup_mma_kernel<<<2112, 256, SMEM_BYTES>>>();
    esup_rowreduce_kernel<<<NR / 8 / 1, 256>>>(z_au, z_tp, fc);
    esup_finalize_kernel<<<1, 1>>>(out);
}

// round 6
// speedup vs baseline: 46.5844x; 1.9188x over previous
#include <cuda_runtime.h>
#include <cuda_fp16.h>
#include <math.h>
#include <stdint.h>

#define NR 8192
#define DD 128
#define ALPHA 2.0f
#define EXPBIAS 96.0f

// ---------------- device globals ----------------
__device__ __align__(128) __half g_au_h[NR * DD];
__device__ __align__(128) __half g_tp_h[NR * DD];
__device__ float g_pos[NR];    // sum_{j!=i} exp(s_aa-B) + exp(s_tt-B)
__device__ float g_neg[NR];    // sum_{j!=i} exp(s_at-B)
__device__ double g_supcon;
__device__ double g_pt;

// ---------------- convert (+zero) kernel: 4 elems/thread ----------------
__global__ void esup_split_kernel(const float* __restrict__ z_au,
                                  const float* __restrict__ z_tp) {
    const int t4 = blockIdx.x * blockDim.x + threadIdx.x;   // 0..262143
    const int base = t4 * 4;
    if (t4 < NR) { g_pos[t4] = 0.0f; g_neg[t4] = 0.0f; }
    if (t4 == 0) { g_supcon = 0.0; g_pt = 0.0; }

    const float4 a = *(const float4*)(z_au + base);
    const float4 b = *(const float4*)(z_tp + base);
    ((__half2*)(g_au_h + base))[0] = __floats2half2_rn(a.x, a.y);
    ((__half2*)(g_au_h + base))[1] = __floats2half2_rn(a.z, a.w);
    ((__half2*)(g_tp_h + base))[0] = __floats2half2_rn(b.x, b.y);
    ((__half2*)(g_tp_h + base))[1] = __floats2half2_rn(b.z, b.w);
}

// ---------------- PTX helpers (baseline ISA, compiles at compute_103) ----------------
__device__ __forceinline__ uint32_t smem_u32(const void* p) {
    uint32_t a;
    asm("{ .reg .u64 t; cvta.to.shared.u64 t, %1; cvt.u32.u64 %0, t; }" : "=r"(a) : "l"(p));
    return a;
}

#define CP_ASYNC16(dst_u32, src_ptr) \
    asm volatile("cp.async.cg.shared.global [%0], [%1], 16;" \
        :: "r"(dst_u32), "l"(src_ptr) : "memory")
#define CP_COMMIT() asm volatile("cp.async.commit_group;" ::: "memory")
#define CP_WAIT1()  asm volatile("cp.async.wait_group 1;" ::: "memory")
#define CP_WAIT0()  asm volatile("cp.async.wait_group 0;" ::: "memory")

__device__ __forceinline__ void ldsm_x4(uint32_t* r, uint32_t addr) {
    asm volatile("ldmatrix.sync.aligned.m8n8.x4.shared.b16 {%0,%1,%2,%3}, [%4];"
        : "=r"(r[0]), "=r"(r[1]), "=r"(r[2]), "=r"(r[3]) : "r"(addr));
}

__device__ __forceinline__ void mma16816(float* c, const uint32_t* a,
                                         uint32_t b0, uint32_t b1) {
    asm volatile("mma.sync.aligned.m16n8k16.row.col.f32.f16.f16.f32 "
        "{%0,%1,%2,%3}, {%4,%5,%6,%7}, {%8,%9}, {%0,%1,%2,%3};"
        : "+f"(c[0]), "+f"(c[1]), "+f"(c[2]), "+f"(c[3])
        : "r"(a[0]), "r"(a[1]), "r"(a[2]), "r"(a[3]), "r"(b0), "r"(b1));
}

// exp(v - EXPBIAS) via single ex2.approx; 138.4987239... = 96 * log2(e)
__device__ __forceinline__ float fexp_b(float v) {
    float r;
    const float t = fmaf(v, 1.4426950408889634f, -138.4987239052529f);
    asm("ex2.approx.f32 %0, %1;" : "=f"(r) : "f"(t));
    return r;
}

// smem tile: [128 rows][16 chunks of 16B], chunk xor-swizzled by (row & 7)
__device__ __forceinline__ uint32_t tile_off(int row, int c) {
    return (uint32_t)(row * 256 + ((c ^ (row & 7)) << 4));
}

// ---------------- main fused GEMM + exp-sum kernel ----------------
// smem: A_hi [0,32K); B stage s at 32K + s*32K; scol at 96K. total 100352 B.
#define SM_A   0u
#define SM_B   32768u
#define SM_COL 98304u
#define SMEM_BYTES 100352

// grid layout: [0,544) job aa triangular, [544,1088) job tt triangular,
// [1088,2112) job at rectangular (64 row tiles x 16 chunks of 4 col tiles)
__global__ __launch_bounds__(256, 2) void esup_mma_kernel() {
    extern __shared__ char smem[];
    const uint32_t sb = smem_u32(smem);
    float* scol = (float*)(smem + SM_COL);       // [512]
    const int tid = threadIdx.x;
    const int lane = tid & 31;
    const int wid = tid >> 5;
    const int wrow = wid & 3;        // 4 warp-rows of 32
    const int wcol = wid >> 2;       // 2 warp-cols of 64

    // ---- bid -> (job, row tile it, chunk) ----
    int job, it, chunk;
    {
        const int bid = blockIdx.x;
        if (bid < 1088) {
            job = (bid < 544) ? 0 : 1;
            int s = (bid < 544) ? bid : bid - 544;
            int itv = 0;
            while (true) {
                const int w = 16 - (itv >> 2);
                if (s < w) break;
                s -= w; ++itv;
            }
            it = itv;
            chunk = (it >> 2) + s;
        } else {
            job = 2;
            const int r = bid - 1088;
            it = r >> 4;
            chunk = r & 15;
        }
    }
    const int i0 = it * 128;
    const int j0base = chunk * 512;

    const __half *Ahi_g, *Bhi_g;
    if (job == 0)      { Ahi_g = g_au_h; Bhi_g = g_au_h; }
    else if (job == 1) { Ahi_g = g_tp_h; Bhi_g = g_tp_h; }
    else               { Ahi_g = g_au_h; Bhi_g = g_tp_h; }

    // zero column accumulator
    scol[tid] = 0.0f;
    scol[tid + 256] = 0.0f;

    // ---- group 0: A tile + B tile 0 ----
    #pragma unroll
    for (int itr = 0; itr < 8; ++itr) {
        const int idx = tid + itr * 256;             // 0..2047
        const int row = idx >> 4, c = idx & 15;
        CP_ASYNC16(sb + SM_A + tile_off(row, c),
                   Ahi_g + (size_t)(i0 + row) * DD + c * 8);
    }
    #pragma unroll
    for (int itr = 0; itr < 8; ++itr) {
        const int idx = tid + itr * 256;
        const int row = idx >> 4, c = idx & 15;
        CP_ASYNC16(sb + SM_B + tile_off(row, c),
                   Bhi_g + (size_t)(j0base + row) * DD + c * 8);
    }
    CP_COMMIT();

    // persistent per-thread row exp-sums: [mt][rh]
    float rs[2][2] = {{0.f, 0.f}, {0.f, 0.f}};

    for (int t = 0; t < 4; ++t) {
        // prefetch next B tile into other stage
        if (t < 3) {
            const uint32_t stg = sb + SM_B + ((t + 1) & 1) * 32768u;
            const int j0n = j0base + (t + 1) * 128;
            #pragma unroll
            for (int itr = 0; itr < 8; ++itr) {
                const int idx = tid + itr * 256;
                const int row = idx >> 4, c = idx & 15;
                CP_ASYNC16(stg + tile_off(row, c),
                           Bhi_g + (size_t)(j0n + row) * DD + c * 8);
            }
            CP_COMMIT();
            CP_WAIT1();
        } else {
            CP_WAIT0();
        }
        __syncthreads();

        const uint32_t bsb = sb + SM_B + (t & 1) * 32768u;
        const int j0 = j0base + t * 128;
        const int jt = chunk * 4 + t;

        float acc[2][8][4];
        #pragma unroll
        for (int mt = 0; mt < 2; ++mt)
            #pragma unroll
            for (int nt = 0; nt < 8; ++nt)
                #pragma unroll
                for (int q = 0; q < 4; ++q) acc[mt][nt][q] = 0.f;

        #pragma unroll
        for (int ks = 0; ks < 8; ++ks) {
            uint32_t Ah[2][4];
            const int arow = wrow * 32 + (lane & 15);
            const int ac = ks * 2 + (lane >> 4);
            #pragma unroll
            for (int mt = 0; mt < 2; ++mt)
                ldsm_x4(Ah[mt], sb + SM_A + tile_off(arow + mt * 16, ac));

            uint32_t Bh[4][4];
            const int bn = wcol * 64 + ((lane >> 4) << 3) + (lane & 7);
            const int bc = ks * 2 + ((lane >> 3) & 1);
            #pragma unroll
            for (int nt2 = 0; nt2 < 4; ++nt2)
                ldsm_x4(Bh[nt2], bsb + tile_off(bn + nt2 * 16, bc));

            #pragma unroll
            for (int mt = 0; mt < 2; ++mt) {
                #pragma unroll
                for (int nt = 0; nt < 8; ++nt) {
                    const uint32_t* bh = &Bh[nt >> 1][(nt & 1) * 2];
                    mma16816(acc[mt][nt], Ah[mt], bh[0], bh[1]);
                }
            }
        }
        __syncthreads();   // stage (t&1) consumed

        // ---- epilogue ----
        const bool do_row = (job == 2) || (jt >= it);
        const bool do_col = (job != 2) && (jt > it);
        const bool dt = (jt == it);
        if (do_row) {
            #pragma unroll
            for (int nt = 0; nt < 8; ++nt) {
                float c0 = 0.f, c1 = 0.f;
                #pragma unroll
                for (int mt = 0; mt < 2; ++mt) {
                    #pragma unroll
                    for (int rh = 0; rh < 2; ++rh) {
                        float v0 = acc[mt][nt][rh * 2 + 0];
                        float v1 = acc[mt][nt][rh * 2 + 1];
                        if (dt) {
                            const int gr = i0 + wrow * 32 + mt * 16 + rh * 8 + (lane >> 2);
                            const int gc0 = j0 + wcol * 64 + nt * 8 + (lane & 3) * 2;
                            if (gr == gc0) v0 = -1e30f;
                            if (gr == gc0 + 1) v1 = -1e30f;
                        }
                        const float e0 = fexp_b(v0);
                        const float e1 = fexp_b(v1);
                        rs[mt][rh] += e0 + e1;
                        c0 += e0; c1 += e1;
                    }
                }
                if (do_col) {
                    // reduce over the 8 lanes sharing (lane & 3): bits 2..4
                    c0 += __shfl_xor_sync(0xFFFFFFFF, c0, 4);
                    c0 += __shfl_xor_sync(0xFFFFFFFF, c0, 8);
                    c0 += __shfl_xor_sync(0xFFFFFFFF, c0, 16);
                    c1 += __shfl_xor_sync(0xFFFFFFFF, c1, 4);
                    c1 += __shfl_xor_sync(0xFFFFFFFF, c1, 8);
                    c1 += __shfl_xor_sync(0xFFFFFFFF, c1, 16);
                    if (lane < 4) {
                        const int lc = t * 128 + wcol * 64 + nt * 8 + lane * 2;
                        atomicAdd(&scol[lc], c0);
                        atomicAdd(&scol[lc + 1], c1);
                    }
                }
            }
        }
    }

    // ---- row flush: quad reduce + global atomics ----
    float* dst = (job == 2) ? g_neg : g_pos;
    #pragma unroll
    for (int mt = 0; mt < 2; ++mt) {
        #pragma unroll
        for (int rh = 0; rh < 2; ++rh) {
            float s = rs[mt][rh];
            s += __shfl_xor_sync(0xFFFFFFFF, s, 1);
            s += __shfl_xor_sync(0xFFFFFFFF, s, 2);
            if ((lane & 3) == 0) {
                const int gr = i0 + wrow * 32 + mt * 16 + rh * 8 + (lane >> 2);
                atomicAdd(dst + gr, s);
            }
        }
    }

    // ---- column flush (symmetric jobs: transpose contribution) ----
    __syncthreads();
    if (job != 2) {
        #pragma unroll
        for (int q = 0; q < 2; ++q) {
            const int idx = tid + q * 256;
            const float v = scol[idx];
            if (v != 0.0f) atomicAdd(&g_pos[j0base + idx], v);
        }
    }
}

// ---------------- per-row reduction: warp per row ----------------
__global__ void esup_rowreduce_kernel(const float* __restrict__ z_au,
                                      const float* __restrict__ z_tp,
                                      const float* __restrict__ fc) {
    __shared__ float sv[8], sp[8];
    const int lane = threadIdx.x & 31;
    const int wid = threadIdx.x >> 5;
    const int row = blockIdx.x * 8 + wid;

    const float4 a = *(const float4*)(z_au + (size_t)row * DD + lane * 4);
    const float4 b = *(const float4*)(z_tp + (size_t)row * DD + lane * 4);
    const float4 w0 = *(const float4*)(fc + lane * 4);
    const float4 w1 = *(const float4*)(fc + DD + lane * 4);

    float diag = a.x * b.x + a.y * b.y + a.z * b.z + a.w * b.w;
    float pt = (a.x - b.x) * (w1.x - w0.x) + (a.y - b.y) * (w1.y - w0.y) +
               (a.z - b.z) * (w1.z - w0.z) + (a.w - b.w) * (w1.w - w0.w);
    #pragma unroll
    for (int s = 16; s > 0; s >>= 1) {
        diag += __shfl_xor_sync(0xFFFFFFFF, diag, s);
        pt   += __shfl_xor_sync(0xFFFFFFFF, pt, s);
    }
    if (lane == 0) {
        const float pos = EXPBIAS + logf(g_pos[row]);
        const float neg = EXPBIAS + logf(g_neg[row]);
        sv[wid] = -pos + neg + ALPHA * diag;
        sp[wid] = pt;
    }
    __syncthreads();
    if (threadIdx.x == 0) {
        double s = 0.0, p = 0.0;
        #pragma unroll
        for (int i = 0; i < 8; ++i) { s += (double)sv[i]; p += (double)sp[i]; }
        atomicAdd(&g_supcon, s);
        atomicAdd(&g_pt, p);
    }
}

__global__ void esup_finalize_kernel(float* out) {
    out[0] = (float)((g_pt / (double)NR + g_supcon) / (double)(NR + 2));
}

// ---------------- launch ----------------
extern "C" void kernel_launch(void* const* d_in, const int* in_sizes, int n_in,
                              void* d_out, int out_size) {
    const float* z_au = (const float*)d_in[0];
    const float* z_tp = (const float*)d_in[1];
    const float* fc   = (const float*)d_in[2];
    float* out = (float*)d_out;

    cudaFuncSetAttribute(esup_mma_kernel,
                         cudaFuncAttributeMaxDynamicSharedMemorySize, SMEM_BYTES);

    esup_split_kernel<<<(NR * DD / 4) / 256, 256>>>(z_au, z_tp);
    esup_mma_kernel<<<2112, 256, SMEM_BYTES>>>();
    esup_rowreduce_kernel<<<NR / 8, 256>>>(z_au, z_tp, fc);
    esup_finalize_kernel<<<1, 1>>>(out);
}

// round 7
// speedup vs baseline: 48.9216x; 1.0502x over previous
#include <cuda_runtime.h>
#include <cuda_fp16.h>
#include <math.h>
#include <stdint.h>

#define NR 8192
#define DD 128
#define ALPHA 2.0f
#define EXPBIAS 96.0f

// ---------------- device globals ----------------
__device__ __align__(128) __half g_au_h[NR * DD];
__device__ __align__(128) __half g_tp_h[NR * DD];
__device__ float g_pos[NR];    // sum_{j!=i} exp(s_aa-B) + exp(s_tt-B)
__device__ float g_neg[NR];    // sum_{j!=i} exp(s_at-B)
__device__ double g_supcon;
__device__ double g_pt;

// ---------------- convert (+zero) kernel: 4 elems/thread ----------------
__global__ void esup_split_kernel(const float* __restrict__ z_au,
                                  const float* __restrict__ z_tp) {
    const int t4 = blockIdx.x * blockDim.x + threadIdx.x;   // 0..262143
    const int base = t4 * 4;
    if (t4 < NR) { g_pos[t4] = 0.0f; g_neg[t4] = 0.0f; }
    if (t4 == 0) { g_supcon = 0.0; g_pt = 0.0; }

    const float4 a = *(const float4*)(z_au + base);
    const float4 b = *(const float4*)(z_tp + base);
    ((__half2*)(g_au_h + base))[0] = __floats2half2_rn(a.x, a.y);
    ((__half2*)(g_au_h + base))[1] = __floats2half2_rn(a.z, a.w);
    ((__half2*)(g_tp_h + base))[0] = __floats2half2_rn(b.x, b.y);
    ((__half2*)(g_tp_h + base))[1] = __floats2half2_rn(b.z, b.w);
}

// ---------------- PTX helpers (baseline ISA, compiles at compute_103) ----------------
__device__ __forceinline__ uint32_t smem_u32(const void* p) {
    uint32_t a;
    asm("{ .reg .u64 t; cvta.to.shared.u64 t, %1; cvt.u32.u64 %0, t; }" : "=r"(a) : "l"(p));
    return a;
}

#define CP_ASYNC16(dst_u32, src_ptr) \
    asm volatile("cp.async.cg.shared.global [%0], [%1], 16;" \
        :: "r"(dst_u32), "l"(src_ptr) : "memory")
#define CP_COMMIT() asm volatile("cp.async.commit_group;" ::: "memory")
#define CP_WAIT1()  asm volatile("cp.async.wait_group 1;" ::: "memory")
#define CP_WAIT0()  asm volatile("cp.async.wait_group 0;" ::: "memory")

__device__ __forceinline__ void ldsm_x4(uint32_t* r, uint32_t addr) {
    asm volatile("ldmatrix.sync.aligned.m8n8.x4.shared.b16 {%0,%1,%2,%3}, [%4];"
        : "=r"(r[0]), "=r"(r[1]), "=r"(r[2]), "=r"(r[3]) : "r"(addr));
}

__device__ __forceinline__ void mma16816(float* c, const uint32_t* a,
                                         uint32_t b0, uint32_t b1) {
    asm volatile("mma.sync.aligned.m16n8k16.row.col.f32.f16.f16.f32 "
        "{%0,%1,%2,%3}, {%4,%5,%6,%7}, {%8,%9}, {%0,%1,%2,%3};"
        : "+f"(c[0]), "+f"(c[1]), "+f"(c[2]), "+f"(c[3])
        : "r"(a[0]), "r"(a[1]), "r"(a[2]), "r"(a[3]), "r"(b0), "r"(b1));
}

// exp(v - EXPBIAS) via single ex2.approx; 138.4987239... = 96 * log2(e)
__device__ __forceinline__ float fexp_b(float v) {
    float r;
    const float t = fmaf(v, 1.4426950408889634f, -138.4987239052529f);
    asm("ex2.approx.f32 %0, %1;" : "=f"(r) : "f"(t));
    return r;
}

// smem tile: [128 rows][16 chunks of 16B], chunk xor-swizzled by (row & 7)
__device__ __forceinline__ uint32_t tile_off(int row, int c) {
    return (uint32_t)(row * 256 + ((c ^ (row & 7)) << 4));
}

// ---------------- main fused GEMM + exp-sum kernel ----------------
// smem: A [0,32K); B stage s at 32K + s*32K; scol at 96K. total 100352 B.
#define SM_A   0u
#define SM_B   32768u
#define SM_COL 98304u
#define SMEM_BYTES 100352

// grid layout: [0,544) job aa triangular, [544,1088) job tt triangular,
// [1088,2112) job at rectangular (64 row tiles x 16 chunks of 4 col tiles)
__global__ __launch_bounds__(256, 2) void esup_mma_kernel() {
    extern __shared__ char smem[];
    const uint32_t sb = smem_u32(smem);
    float* scol = (float*)(smem + SM_COL);       // [512]
    const int tid = threadIdx.x;
    const int lane = tid & 31;
    const int wid = tid >> 5;
    const int wrow = wid & 3;        // 4 warp-rows of 32
    const int wcol = wid >> 2;       // 2 warp-cols of 64

    // ---- bid -> (job, row tile it, chunk) ----
    int job, it, chunk;
    {
        const int bid = blockIdx.x;
        if (bid < 1088) {
            job = (bid < 544) ? 0 : 1;
            int s = (bid < 544) ? bid : bid - 544;
            int itv = 0;
            while (true) {
                const int w = 16 - (itv >> 2);
                if (s < w) break;
                s -= w; ++itv;
            }
            it = itv;
            chunk = (it >> 2) + s;
        } else {
            job = 2;
            const int r = bid - 1088;
            it = r >> 4;
            chunk = r & 15;
        }
    }
    const int i0 = it * 128;
    const int j0base = chunk * 512;

    const __half *Ahi_g, *Bhi_g;
    if (job == 0)      { Ahi_g = g_au_h; Bhi_g = g_au_h; }
    else if (job == 1) { Ahi_g = g_tp_h; Bhi_g = g_tp_h; }
    else               { Ahi_g = g_au_h; Bhi_g = g_tp_h; }

    // zero column accumulator (symmetric jobs only)
    if (job != 2) {
        scol[tid] = 0.0f;
        scol[tid + 256] = 0.0f;
    }

    // ---- group 0: A tile + B tile 0 ----
    #pragma unroll
    for (int itr = 0; itr < 8; ++itr) {
        const int idx = tid + itr * 256;             // 0..2047
        const int row = idx >> 4, c = idx & 15;
        CP_ASYNC16(sb + SM_A + tile_off(row, c),
                   Ahi_g + (size_t)(i0 + row) * DD + c * 8);
    }
    #pragma unroll
    for (int itr = 0; itr < 8; ++itr) {
        const int idx = tid + itr * 256;
        const int row = idx >> 4, c = idx & 15;
        CP_ASYNC16(sb + SM_B + tile_off(row, c),
                   Bhi_g + (size_t)(j0base + row) * DD + c * 8);
    }
    CP_COMMIT();

    // persistent per-thread row exp-sums: [mt][rh]
    float rs[2][2] = {{0.f, 0.f}, {0.f, 0.f}};

    // hoisted fragment addressing bases
    const int arow0 = wrow * 32 + (lane & 15);
    const int bn0 = wcol * 64 + ((lane >> 4) << 3) + (lane & 7);

    for (int t = 0; t < 4; ++t) {
        // prefetch next B tile into other stage
        if (t < 3) {
            const uint32_t stg = sb + SM_B + ((t + 1) & 1) * 32768u;
            const int j0n = j0base + (t + 1) * 128;
            #pragma unroll
            for (int itr = 0; itr < 8; ++itr) {
                const int idx = tid + itr * 256;
                const int row = idx >> 4, c = idx & 15;
                CP_ASYNC16(stg + tile_off(row, c),
                           Bhi_g + (size_t)(j0n + row) * DD + c * 8);
            }
            CP_COMMIT();
            CP_WAIT1();
        } else {
            CP_WAIT0();
        }
        __syncthreads();

        const uint32_t bsb = sb + SM_B + (t & 1) * 32768u;
        const int j0 = j0base + t * 128;
        const int jt = chunk * 4 + t;

        float acc[2][8][4];
        #pragma unroll
        for (int mt = 0; mt < 2; ++mt)
            #pragma unroll
            for (int nt = 0; nt < 8; ++nt)
                #pragma unroll
                for (int q = 0; q < 4; ++q) acc[mt][nt][q] = 0.f;

        #pragma unroll
        for (int ks = 0; ks < 8; ++ks) {
            uint32_t Ah[2][4];
            const int ac = ks * 2 + (lane >> 4);
            #pragma unroll
            for (int mt = 0; mt < 2; ++mt)
                ldsm_x4(Ah[mt], sb + SM_A + tile_off(arow0 + mt * 16, ac));

            const int bc = ks * 2 + ((lane >> 3) & 1);
            #pragma unroll
            for (int nt2 = 0; nt2 < 4; ++nt2) {
                uint32_t Bh[4];                               // live briefly
                ldsm_x4(Bh, bsb + tile_off(bn0 + nt2 * 16, bc));
                #pragma unroll
                for (int mt = 0; mt < 2; ++mt) {
                    mma16816(acc[mt][nt2 * 2 + 0], Ah[mt], Bh[0], Bh[1]);
                    mma16816(acc[mt][nt2 * 2 + 1], Ah[mt], Bh[2], Bh[3]);
                }
            }
        }
        __syncthreads();   // stage (t&1) consumed

        // ---- epilogue (specialized paths) ----
        if (job != 2 && jt > it) {
            // strictly upper triangular: row + column sums, no diag mask
            #pragma unroll
            for (int nt = 0; nt < 8; ++nt) {
                float c0 = 0.f, c1 = 0.f;
                #pragma unroll
                for (int mt = 0; mt < 2; ++mt) {
                    #pragma unroll
                    for (int rh = 0; rh < 2; ++rh) {
                        const float e0 = fexp_b(acc[mt][nt][rh * 2 + 0]);
                        const float e1 = fexp_b(acc[mt][nt][rh * 2 + 1]);
                        rs[mt][rh] += e0 + e1;
                        c0 += e0; c1 += e1;
                    }
                }
                // reduce over the 8 lanes sharing (lane & 3): bits 2..4
                c0 += __shfl_xor_sync(0xFFFFFFFF, c0, 4);
                c0 += __shfl_xor_sync(0xFFFFFFFF, c0, 8);
                c0 += __shfl_xor_sync(0xFFFFFFFF, c0, 16);
                c1 += __shfl_xor_sync(0xFFFFFFFF, c1, 4);
                c1 += __shfl_xor_sync(0xFFFFFFFF, c1, 8);
                c1 += __shfl_xor_sync(0xFFFFFFFF, c1, 16);
                if (lane < 4) {
                    const int lc = t * 128 + wcol * 64 + nt * 8 + lane * 2;
                    atomicAdd(&scol[lc], c0);
                    atomicAdd(&scol[lc + 1], c1);
                }
            }
        } else if (job == 2 || jt == it) {
            // row-only path (at job, or diagonal tiles of symmetric jobs)
            const bool dt = (jt == it);
            #pragma unroll
            for (int nt = 0; nt < 8; ++nt) {
                #pragma unroll
                for (int mt = 0; mt < 2; ++mt) {
                    #pragma unroll
                    for (int rh = 0; rh < 2; ++rh) {
                        float v0 = acc[mt][nt][rh * 2 + 0];
                        float v1 = acc[mt][nt][rh * 2 + 1];
                        if (dt) {
                            const int gr = i0 + wrow * 32 + mt * 16 + rh * 8 + (lane >> 2);
                            const int gc0 = j0 + wcol * 64 + nt * 8 + (lane & 3) * 2;
                            if (gr == gc0) v0 = -1e30f;
                            if (gr == gc0 + 1) v1 = -1e30f;
                        }
                        rs[mt][rh] += fexp_b(v0) + fexp_b(v1);
                    }
                }
            }
        }
        // jt < it on symmetric jobs: tile discarded (covered by transpose)
    }

    // ---- row flush: quad reduce + global atomics ----
    float* dst = (job == 2) ? g_neg : g_pos;
    #pragma unroll
    for (int mt = 0; mt < 2; ++mt) {
        #pragma unroll
        for (int rh = 0; rh < 2; ++rh) {
            float s = rs[mt][rh];
            s += __shfl_xor_sync(0xFFFFFFFF, s, 1);
            s += __shfl_xor_sync(0xFFFFFFFF, s, 2);
            if ((lane & 3) == 0) {
                const int gr = i0 + wrow * 32 + mt * 16 + rh * 8 + (lane >> 2);
                atomicAdd(dst + gr, s);
            }
        }
    }

    // ---- column flush (symmetric jobs: transpose contribution) ----
    if (job != 2) {
        __syncthreads();
        #pragma unroll
        for (int q = 0; q < 2; ++q) {
            const int idx = tid + q * 256;
            const float v = scol[idx];
            if (v != 0.0f) atomicAdd(&g_pos[j0base + idx], v);
        }
    }
}

// ---------------- per-row reduction: warp per row ----------------
__global__ void esup_rowreduce_kernel(const float* __restrict__ z_au,
                                      const float* __restrict__ z_tp,
                                      const float* __restrict__ fc) {
    __shared__ float sv[8], sp[8];
    const int lane = threadIdx.x & 31;
    const int wid = threadIdx.x >> 5;
    const int row = blockIdx.x * 8 + wid;

    const float4 a = *(const float4*)(z_au + (size_t)row * DD + lane * 4);
    const float4 b = *(const float4*)(z_tp + (size_t)row * DD + lane * 4);
    const float4 w0 = *(const float4*)(fc + lane * 4);
    const float4 w1 = *(const float4*)(fc + DD + lane * 4);

    float diag = a.x * b.x + a.y * b.y + a.z * b.z + a.w * b.w;
    float pt = (a.x - b.x) * (w1.x - w0.x) + (a.y - b.y) * (w1.y - w0.y) +
               (a.z - b.z) * (w1.z - w0.z) + (a.w - b.w) * (w1.w - w0.w);
    #pragma unroll
    for (int s = 16; s > 0; s >>= 1) {
        diag += __shfl_xor_sync(0xFFFFFFFF, diag, s);
        pt   += __shfl_xor_sync(0xFFFFFFFF, pt, s);
    }
    if (lane == 0) {
        const float pos = EXPBIAS + logf(g_pos[row]);
        const float neg = EXPBIAS + logf(g_neg[row]);
        sv[wid] = -pos + neg + ALPHA * diag;
        sp[wid] = pt;
    }
    __syncthreads();
    if (threadIdx.x == 0) {
        double s = 0.0, p = 0.0;
        #pragma unroll
        for (int i = 0; i < 8; ++i) { s += (double)sv[i]; p += (double)sp[i]; }
        atomicAdd(&g_supcon, s);
        atomicAdd(&g_pt, p);
    }
}

__global__ void esup_finalize_kernel(float* out) {
    out[0] = (float)((g_pt / (double)NR + g_supcon) / (double)(NR + 2));
}

// ---------------- launch ----------------
extern "C" void kernel_launch(void* const* d_in, const int* in_sizes, int n_in,
                              void* d_out, int out_size) {
    const float* z_au = (const float*)d_in[0];
    const float* z_tp = (const float*)d_in[1];
    const float* fc   = (const float*)d_in[2];
    float* out = (float*)d_out;

    cudaFuncSetAttribute(esup_mma_kernel,
                         cudaFuncAttributeMaxDynamicSharedMemorySize, SMEM_BYTES);

    esup_split_kernel<<<(NR * DD / 4) / 256, 256>>>(z_au, z_tp);
    esup_mma_kernel<<<2112, 256, SMEM_BYTES>>>();
    esup_rowreduce_kernel<<<NR / 8, 256>>>(z_au, z_tp, fc);
    esup_finalize_kernel<<<1, 1>>>(out);
}

// round 8
// speedup vs baseline: 49.8563x; 1.0191x over previous
#include <cuda_runtime.h>
#include <cuda_fp16.h>
#include <math.h>
#include <stdint.h>

#define NR 8192
#define DD 128
#define ALPHA 2.0f
#define EXPBIAS 96.0f

// ---------------- device globals ----------------
__device__ __align__(128) __half g_au_h[NR * DD];
__device__ __align__(128) __half g_tp_h[NR * DD];
__device__ float g_pos[NR];    // sum_{j!=i} exp(s_aa-B) + exp(s_tt-B)
__device__ float g_neg[NR];    // sum_{j!=i} exp(s_at-B)
__device__ double g_supcon;
__device__ double g_pt;
__device__ unsigned g_done;

// ---------------- convert (+zero) kernel: 4 elems/thread ----------------
__global__ void esup_split_kernel(const float* __restrict__ z_au,
                                  const float* __restrict__ z_tp) {
    const int t4 = blockIdx.x * blockDim.x + threadIdx.x;   // 0..262143
    const int base = t4 * 4;
    if (t4 < NR) { g_pos[t4] = 0.0f; g_neg[t4] = 0.0f; }
    if (t4 == 0) { g_supcon = 0.0; g_pt = 0.0; g_done = 0u; }

    const float4 a = *(const float4*)(z_au + base);
    const float4 b = *(const float4*)(z_tp + base);
    ((__half2*)(g_au_h + base))[0] = __floats2half2_rn(a.x, a.y);
    ((__half2*)(g_au_h + base))[1] = __floats2half2_rn(a.z, a.w);
    ((__half2*)(g_tp_h + base))[0] = __floats2half2_rn(b.x, b.y);
    ((__half2*)(g_tp_h + base))[1] = __floats2half2_rn(b.z, b.w);
}

// ---------------- PTX helpers (baseline ISA, compiles at compute_103) ----------------
__device__ __forceinline__ uint32_t smem_u32(const void* p) {
    uint32_t a;
    asm("{ .reg .u64 t; cvta.to.shared.u64 t, %1; cvt.u32.u64 %0, t; }" : "=r"(a) : "l"(p));
    return a;
}

#define CP_ASYNC16(dst_u32, src_ptr) \
    asm volatile("cp.async.cg.shared.global [%0], [%1], 16;" \
        :: "r"(dst_u32), "l"(src_ptr) : "memory")

// mbarrier (sm_80 baseline)
#define MBAR_INIT(addr, cnt) \
    asm volatile("mbarrier.init.shared.b64 [%0], %1;" :: "r"((uint32_t)(addr)), "r"((uint32_t)(cnt)) : "memory")
#define MBAR_ARRIVE(addr) \
    asm volatile("mbarrier.arrive.shared.b64 _, [%0];" :: "r"((uint32_t)(addr)) : "memory")
#define CP_ARRIVE_NOINC(addr) \
    asm volatile("cp.async.mbarrier.arrive.noinc.shared.b64 [%0];" :: "r"((uint32_t)(addr)) : "memory")
#define MBAR_WAIT(addr, par) do {                                                 \
    uint32_t _m = (uint32_t)(addr); uint32_t _p = (uint32_t)(par); uint32_t _d;   \
    asm volatile("{\n\t.reg .pred p;\n\t"                                         \
        "mbarrier.try_wait.parity.shared.b64 p, [%1], %2;\n\t"                    \
        "selp.b32 %0, 1, 0, p;\n\t}"                                              \
        : "=r"(_d) : "r"(_m), "r"(_p) : "memory");                                \
    if (!_d) {                                                                    \
        asm volatile("{\n\t.reg .pred P1;\n\t"                                    \
            "WL_%=:\n\t"                                                          \
            "mbarrier.try_wait.parity.shared.b64 P1, [%0], %1;\n\t"               \
            "@P1 bra.uni WD_%=;\n\t"                                              \
            "bra.uni WL_%=;\n\t"                                                  \
            "WD_%=:\n\t}" :: "r"(_m), "r"(_p) : "memory");                        \
    }                                                                             \
} while (0)

__device__ __forceinline__ void ldsm_x4(uint32_t* r, uint32_t addr) {
    asm volatile("ldmatrix.sync.aligned.m8n8.x4.shared.b16 {%0,%1,%2,%3}, [%4];"
        : "=r"(r[0]), "=r"(r[1]), "=r"(r[2]), "=r"(r[3]) : "r"(addr));
}

__device__ __forceinline__ void mma16816(float* c, const uint32_t* a,
                                         uint32_t b0, uint32_t b1) {
    asm volatile("mma.sync.aligned.m16n8k16.row.col.f32.f16.f16.f32 "
        "{%0,%1,%2,%3}, {%4,%5,%6,%7}, {%8,%9}, {%0,%1,%2,%3};"
        : "+f"(c[0]), "+f"(c[1]), "+f"(c[2]), "+f"(c[3])
        : "r"(a[0]), "r"(a[1]), "r"(a[2]), "r"(a[3]), "r"(b0), "r"(b1));
}

// exp(v - EXPBIAS) via single ex2.approx; 138.4987239... = 96 * log2(e)
__device__ __forceinline__ float fexp_b(float v) {
    float r;
    const float t = fmaf(v, 1.4426950408889634f, -138.4987239052529f);
    asm("ex2.approx.f32 %0, %1;" : "=f"(r) : "f"(t));
    return r;
}

// smem tile: [128 rows][16 chunks of 16B], chunk xor-swizzled by (row & 7)
__device__ __forceinline__ uint32_t tile_off(int row, int c) {
    return (uint32_t)(row * 256 + ((c ^ (row & 7)) << 4));
}

// ---------------- main fused GEMM + exp-sum kernel ----------------
// smem: A [0,32K); B stage s at 32K + s*32K; scol at 96K; mbars at 98K+2K.
#define SM_A    0u
#define SM_B    32768u
#define SM_COL  98304u
#define SM_MBAR 100352u     // full0, full1, empty0, empty1 (8B each)
#define SMEM_BYTES 100416

// grid layout: [0,544) job aa triangular, [544,1088) job tt triangular,
// [1088,2112) job at rectangular (64 row tiles x 16 chunks of 4 col tiles)
__global__ __launch_bounds__(256, 2) void esup_mma_kernel() {
    extern __shared__ char smem[];
    const uint32_t sb = smem_u32(smem);
    float* scol = (float*)(smem + SM_COL);       // [512]
    const int tid = threadIdx.x;
    const int lane = tid & 31;
    const int wid = tid >> 5;
    const int wrow = wid & 3;        // 4 warp-rows of 32
    const int wcol = wid >> 2;       // 2 warp-cols of 64

    // ---- bid -> (job, row tile it, chunk) ----
    int job, it, chunk;
    {
        const int bid = blockIdx.x;
        if (bid < 1088) {
            job = (bid < 544) ? 0 : 1;
            int s = (bid < 544) ? bid : bid - 544;
            int itv = 0;
            while (true) {
                const int w = 16 - (itv >> 2);
                if (s < w) break;
                s -= w; ++itv;
            }
            it = itv;
            chunk = (it >> 2) + s;
        } else {
            job = 2;
            const int r = bid - 1088;
            it = r >> 4;
            chunk = r & 15;
        }
    }
    const int i0 = it * 128;
    const int j0base = chunk * 512;

    const __half *Ahi_g, *Bhi_g;
    if (job == 0)      { Ahi_g = g_au_h; Bhi_g = g_au_h; }
    else if (job == 1) { Ahi_g = g_tp_h; Bhi_g = g_tp_h; }
    else               { Ahi_g = g_au_h; Bhi_g = g_tp_h; }

    // mbarrier init + scol zero
    if (tid == 0) {
        MBAR_INIT(sb + SM_MBAR + 0,  256);   // full0
        MBAR_INIT(sb + SM_MBAR + 8,  256);   // full1
        MBAR_INIT(sb + SM_MBAR + 16, 256);   // empty0
        MBAR_INIT(sb + SM_MBAR + 24, 256);   // empty1
    }
    if (job != 2) {
        scol[tid] = 0.0f;
        scol[tid + 256] = 0.0f;
    }
    __syncthreads();

    // ---- prologue: A tile + B tile 0, arrive full0 on completion ----
    #pragma unroll
    for (int itr = 0; itr < 8; ++itr) {
        const int idx = tid + itr * 256;             // 0..2047
        const int row = idx >> 4, c = idx & 15;
        CP_ASYNC16(sb + SM_A + tile_off(row, c),
                   Ahi_g + (size_t)(i0 + row) * DD + c * 8);
    }
    #pragma unroll
    for (int itr = 0; itr < 8; ++itr) {
        const int idx = tid + itr * 256;
        const int row = idx >> 4, c = idx & 15;
        CP_ASYNC16(sb + SM_B + tile_off(row, c),
                   Bhi_g + (size_t)(j0base + row) * DD + c * 8);
    }
    CP_ARRIVE_NOINC(sb + SM_MBAR + 0);

    // persistent per-thread row exp-sums: [mt][rh]
    float rs[2][2] = {{0.f, 0.f}, {0.f, 0.f}};

    // hoisted fragment addressing bases
    const int arow0 = wrow * 32 + (lane & 15);
    const int bn0 = wcol * 64 + ((lane >> 4) << 3) + (lane & 7);

    // pipeline cursors
    int fs = 0, fp = 0;        // full: consumer, starts (0, ph0)
    int es = 1, ep = 1;        // empty: producer, starts (1, ph1) -> first wait passes

    for (int t = 0; t < 4; ++t) {
        // prefetch next B tile (per-thread, no CTA barrier)
        if (t < 3) {
            MBAR_WAIT(sb + SM_MBAR + 16 + es * 8, ep);
            const uint32_t stg = sb + SM_B + es * 32768u;
            const int j0n = j0base + (t + 1) * 128;
            #pragma unroll
            for (int itr = 0; itr < 8; ++itr) {
                const int idx = tid + itr * 256;
                const int row = idx >> 4, c = idx & 15;
                CP_ASYNC16(stg + tile_off(row, c),
                           Bhi_g + (size_t)(j0n + row) * DD + c * 8);
            }
            CP_ARRIVE_NOINC(sb + SM_MBAR + es * 8);
            if (++es == 2) { es = 0; ep ^= 1; }
        }

        // wait current stage full
        MBAR_WAIT(sb + SM_MBAR + fs * 8, fp);
        if (++fs == 2) { fs = 0; fp ^= 1; }

        const uint32_t bsb = sb + SM_B + (t & 1) * 32768u;
        const int j0 = j0base + t * 128;
        const int jt = chunk * 4 + t;

        float acc[2][8][4];
        #pragma unroll
        for (int mt = 0; mt < 2; ++mt)
            #pragma unroll
            for (int nt = 0; nt < 8; ++nt)
                #pragma unroll
                for (int q = 0; q < 4; ++q) acc[mt][nt][q] = 0.f;

        #pragma unroll
        for (int ks = 0; ks < 8; ++ks) {
            uint32_t Ah[2][4];
            const int ac = ks * 2 + (lane >> 4);
            #pragma unroll
            for (int mt = 0; mt < 2; ++mt)
                ldsm_x4(Ah[mt], sb + SM_A + tile_off(arow0 + mt * 16, ac));

            const int bc = ks * 2 + ((lane >> 3) & 1);
            #pragma unroll
            for (int nt2 = 0; nt2 < 4; ++nt2) {
                uint32_t Bh[4];                               // live briefly
                ldsm_x4(Bh, bsb + tile_off(bn0 + nt2 * 16, bc));
                #pragma unroll
                for (int mt = 0; mt < 2; ++mt) {
                    mma16816(acc[mt][nt2 * 2 + 0], Ah[mt], Bh[0], Bh[1]);
                    mma16816(acc[mt][nt2 * 2 + 1], Ah[mt], Bh[2], Bh[3]);
                }
            }
        }
        // stage consumed: free it for producers
        MBAR_ARRIVE(sb + SM_MBAR + 16 + (t & 1) * 8);

        // ---- epilogue (no CTA barrier — overlaps other warps' k-loops) ----
        if (job != 2 && jt > it) {
            // strictly upper triangular: row + column sums, no diag mask
            #pragma unroll
            for (int nt = 0; nt < 8; ++nt) {
                float c0 = 0.f, c1 = 0.f;
                #pragma unroll
                for (int mt = 0; mt < 2; ++mt) {
                    #pragma unroll
                    for (int rh = 0; rh < 2; ++rh) {
                        const float e0 = fexp_b(acc[mt][nt][rh * 2 + 0]);
                        const float e1 = fexp_b(acc[mt][nt][rh * 2 + 1]);
                        rs[mt][rh] += e0 + e1;
                        c0 += e0; c1 += e1;
                    }
                }
                // reduce over the 8 lanes sharing (lane & 3): bits 2..4
                c0 += __shfl_xor_sync(0xFFFFFFFF, c0, 4);
                c0 += __shfl_xor_sync(0xFFFFFFFF, c0, 8);
                c0 += __shfl_xor_sync(0xFFFFFFFF, c0, 16);
                c1 += __shfl_xor_sync(0xFFFFFFFF, c1, 4);
                c1 += __shfl_xor_sync(0xFFFFFFFF, c1, 8);
                c1 += __shfl_xor_sync(0xFFFFFFFF, c1, 16);
                if (lane < 4) {
                    const int lc = t * 128 + wcol * 64 + nt * 8 + lane * 2;
                    atomicAdd(&scol[lc], c0);
                    atomicAdd(&scol[lc + 1], c1);
                }
            }
        } else if (job == 2 || jt == it) {
            // row-only path (at job, or diagonal tiles of symmetric jobs)
            const bool dt = (jt == it);
            #pragma unroll
            for (int nt = 0; nt < 8; ++nt) {
                #pragma unroll
                for (int mt = 0; mt < 2; ++mt) {
                    #pragma unroll
                    for (int rh = 0; rh < 2; ++rh) {
                        float v0 = acc[mt][nt][rh * 2 + 0];
                        float v1 = acc[mt][nt][rh * 2 + 1];
                        if (dt) {
                            const int gr = i0 + wrow * 32 + mt * 16 + rh * 8 + (lane >> 2);
                            const int gc0 = j0 + wcol * 64 + nt * 8 + (lane & 3) * 2;
                            if (gr == gc0) v0 = -1e30f;
                            if (gr == gc0 + 1) v1 = -1e30f;
                        }
                        rs[mt][rh] += fexp_b(v0) + fexp_b(v1);
                    }
                }
            }
        }
        // jt < it on symmetric jobs: tile discarded (covered by transpose)
    }

    // ---- row flush: quad reduce + global atomics ----
    float* dst = (job == 2) ? g_neg : g_pos;
    #pragma unroll
    for (int mt = 0; mt < 2; ++mt) {
        #pragma unroll
        for (int rh = 0; rh < 2; ++rh) {
            float s = rs[mt][rh];
            s += __shfl_xor_sync(0xFFFFFFFF, s, 1);
            s += __shfl_xor_sync(0xFFFFFFFF, s, 2);
            if ((lane & 3) == 0) {
                const int gr = i0 + wrow * 32 + mt * 16 + rh * 8 + (lane >> 2);
                atomicAdd(dst + gr, s);
            }
        }
    }

    // ---- column flush (symmetric jobs: transpose contribution) ----
    if (job != 2) {
        __syncthreads();
        #pragma unroll
        for (int q = 0; q < 2; ++q) {
            const int idx = tid + q * 256;
            const float v = scol[idx];
            if (v != 0.0f) atomicAdd(&g_pos[j0base + idx], v);
        }
    }
}

// ---------------- per-row reduction (+ fused finalize) ----------------
__global__ void esup_rowreduce_kernel(const float* __restrict__ z_au,
                                      const float* __restrict__ z_tp,
                                      const float* __restrict__ fc,
                                      float* __restrict__ out) {
    __shared__ float sv[8], sp[8];
    const int lane = threadIdx.x & 31;
    const int wid = threadIdx.x >> 5;
    const int row = blockIdx.x * 8 + wid;

    const float4 a = *(const float4*)(z_au + (size_t)row * DD + lane * 4);
    const float4 b = *(const float4*)(z_tp + (size_t)row * DD + lane * 4);
    const float4 w0 = *(const float4*)(fc + lane * 4);
    const float4 w1 = *(const float4*)(fc + DD + lane * 4);

    float diag = a.x * b.x + a.y * b.y + a.z * b.z + a.w * b.w;
    float pt = (a.x - b.x) * (w1.x - w0.x) + (a.y - b.y) * (w1.y - w0.y) +
               (a.z - b.z) * (w1.z - w0.z) + (a.w - b.w) * (w1.w - w0.w);
    #pragma unroll
    for (int s = 16; s > 0; s >>= 1) {
        diag += __shfl_xor_sync(0xFFFFFFFF, diag, s);
        pt   += __shfl_xor_sync(0xFFFFFFFF, pt, s);
    }
    if (lane == 0) {
        const float pos = EXPBIAS + logf(g_pos[row]);
        const float neg = EXPBIAS + logf(g_neg[row]);
        sv[wid] = -pos + neg + ALPHA * diag;
        sp[wid] = pt;
    }
    __syncthreads();
    if (threadIdx.x == 0) {
        double s = 0.0, p = 0.0;
        #pragma unroll
        for (int i = 0; i < 8; ++i) { s += (double)sv[i]; p += (double)sp[i]; }
        atomicAdd(&g_supcon, s);
        atomicAdd(&g_pt, p);
        __threadfence();
        const unsigned prev = atomicAdd(&g_done, 1u);
        if (prev == gridDim.x - 1) {
            const double st = atomicAdd(&g_supcon, 0.0);
            const double pp = atomicAdd(&g_pt, 0.0);
            out[0] = (float)((pp / (double)NR + st) / (double)(NR + 2));
        }
    }
}

// ---------------- launch ----------------
extern "C" void kernel_launch(void* const* d_in, const int* in_sizes, int n_in,
                              void* d_out, int out_size) {
    const float* z_au = (const float*)d_in[0];
    const float* z_tp = (const float*)d_in[1];
    const float* fc   = (const float*)d_in[2];
    float* out = (float*)d_out;

    cudaFuncSetAttribute(esup_mma_kernel,
                         cudaFuncAttributeMaxDynamicSharedMemorySize, SMEM_BYTES);

    esup_split_kernel<<<(NR * DD / 4) / 256, 256>>>(z_au, z_tp);
    esup_mma_kernel<<<2112, 256, SMEM_BYTES>>>();
    esup_rowreduce_kernel<<<NR / 8, 256>>>(z_au, z_tp, fc, out);
}